// round 5
// baseline (speedup 1.0000x reference)
#include <cuda_runtime.h>
#include <cuda_bf16.h>
#include <cstdint>

#define N_NODES 100000
#define N_GRAPHS 64
#define MAX_E    1600000
#define SCAN_B   1024
#define N_SCANB  ((N_NODES + SCAN_B - 1) / SCAN_B)   // 98

// ---------------- scratch (device globals; no allocation allowed) ----------
__device__ int   g_flag64;               // 1 if index buffers are int64
__device__ int   g_batch[N_NODES];
__device__ int   g_indeg[N_NODES];
__device__ float g_dinv[N_NODES];
__device__ int   g_row_ptr[N_NODES + 1];
__device__ int   g_cur[N_NODES];
__device__ int   g_blocksum[N_SCANB];
__device__ int   g_blockoff[N_SCANB];
__device__ __align__(16) int2  g_csr[MAX_E];           // {src, nrm as int}
__device__ __align__(16) float g_h[N_NODES * 64];      // h1 activations
__device__ __align__(16) float g_y[N_NODES * 32];      // layer-3 pre-agg (stride 32, 24 used)
__device__ float g_sums[N_GRAPHS * 24];
__device__ float g_cnt[N_GRAPHS];

// ---------------- detect dtype + zero pool accumulators ---------------------
// int64 indices (< 2^31) => every odd 32-bit word is zero. 2048 samples.
__global__ void detect_zero_kernel(const int* __restrict__ buf, int samples) {
    __shared__ int s_nz[256];
    int t = threadIdx.x;
    int nz = 0;
    for (int i = t; i < samples; i += 256) nz |= buf[2 * i + 1];
    s_nz[t] = nz;
    __syncthreads();
    for (int off = 128; off > 0; off >>= 1) {
        if (t < off) s_nz[t] |= s_nz[t + off];
        __syncthreads();
    }
    if (t == 0) g_flag64 = (s_nz[0] == 0) ? 1 : 0;
    for (int i = t; i < N_GRAPHS * 24; i += 256) g_sums[i] = 0.0f;
    if (t < N_GRAPHS) g_cnt[t] = 0.0f;
}

__device__ __forceinline__ int load_idx(const int* __restrict__ buf, long long i) {
    return g_flag64 ? buf[2 * i] : buf[(int)i];
}

// ---------------- batch convert + per-graph counts + zero indeg -------------
__global__ void convert_kernel(const int* __restrict__ buf) {
    __shared__ float scnt[N_GRAPHS];
    int t = threadIdx.x;
    if (t < N_GRAPHS) scnt[t] = 0.0f;
    __syncthreads();
    int v = blockIdx.x * blockDim.x + t;
    if (v < N_NODES) {
        int g = load_idx(buf, v);
        g_batch[v] = g;
        g_indeg[v] = 0;
        atomicAdd(&scnt[g], 1.0f);
    }
    __syncthreads();
    if (t < N_GRAPHS && scnt[t] != 0.0f) atomicAdd(&g_cnt[t], scnt[t]);
}

// ---------------- degree ------------------------------------------------------
__global__ void count_deg_kernel(const int* __restrict__ ei, int E) {
    int e = blockIdx.x * blockDim.x + threadIdx.x;
    if (e < E) {
        int d = load_idx(ei, (long long)E + e);
        atomicAdd(&g_indeg[d], 1);
    }
}

// ---------------- scan (exclusive prefix sum of indeg -> row_ptr) -------------
__global__ void scan1_kernel() {
    __shared__ int s[SCAN_B];
    int t = threadIdx.x;
    int i = blockIdx.x * SCAN_B + t;
    int v = (i < N_NODES) ? g_indeg[i] : 0;
    if (i < N_NODES) g_dinv[i] = rsqrtf((float)(v + 1));   // +1 self-loop
    s[t] = v;
    __syncthreads();
#pragma unroll
    for (int off = 1; off < SCAN_B; off <<= 1) {
        int x = (t >= off) ? s[t - off] : 0;
        __syncthreads();
        s[t] += x;
        __syncthreads();
    }
    if (i < N_NODES) g_row_ptr[i] = s[t] - v;   // exclusive
    if (t == SCAN_B - 1) g_blocksum[blockIdx.x] = s[t];
}

__global__ void scan2_kernel() {
    int lane = threadIdx.x;   // one warp
    int acc = 0;
    for (int base = 0; base < N_SCANB; base += 32) {
        int i = base + lane;
        int v0 = (i < N_SCANB) ? g_blocksum[i] : 0;
        int v = v0;
#pragma unroll
        for (int off = 1; off < 32; off <<= 1) {
            int x = __shfl_up_sync(0xFFFFFFFFu, v, off);
            if (lane >= off) v += x;
        }
        if (i < N_SCANB) g_blockoff[i] = acc + v - v0;   // exclusive
        acc += __shfl_sync(0xFFFFFFFFu, v, 31);
    }
}

__global__ void scan3_kernel(int E) {
    int i = blockIdx.x * blockDim.x + threadIdx.x;
    if (i < N_NODES) {
        int r = g_row_ptr[i] + g_blockoff[i / SCAN_B];
        g_row_ptr[i] = r;
        g_cur[i] = r;
    }
    if (i == 0) g_row_ptr[N_NODES] = E;
}

// ---------------- CSR fill ----------------------------------------------------
__global__ void fill_csr_kernel(const int* __restrict__ ei, int E) {
    int e = blockIdx.x * blockDim.x + threadIdx.x;
    if (e >= E) return;
    int s = load_idx(ei, e);
    int d = load_idx(ei, (long long)E + e);
    int pos = atomicAdd(&g_cur[d], 1);
    float nrm = g_dinv[s] * g_dinv[d];
    g_csr[pos] = make_int2(s, __float_as_int(nrm));
}

// ---------------- layer 1: gather(pos,3) + GEMM 3->64 + ReLU ------------------
__global__ void __launch_bounds__(128)
layer1_kernel(const float* __restrict__ pos, const float* __restrict__ W1,
              const float* __restrict__ b1, float* __restrict__ h1) {
    __shared__ float sW[3 * 64];
    __shared__ float sb[64];
    for (int i = threadIdx.x; i < 3 * 64; i += 128) sW[i] = W1[i];
    if (threadIdx.x < 64) sb[threadIdx.x] = b1[threadIdx.x];
    __syncthreads();
    int v = blockIdx.x * 128 + threadIdx.x;
    if (v >= N_NODES) return;
    float di = g_dinv[v];
    float self = di * di;
    float a0 = self * pos[3 * v + 0];
    float a1 = self * pos[3 * v + 1];
    float a2 = self * pos[3 * v + 2];
    int e = g_row_ptr[v], end = g_row_ptr[v + 1];
    for (; e + 4 <= end; e += 4) {
        int2 p0 = g_csr[e], p1 = g_csr[e + 1], p2 = g_csr[e + 2], p3 = g_csr[e + 3];
        const float* s0 = pos + (long long)p0.x * 3;
        const float* s1 = pos + (long long)p1.x * 3;
        const float* s2 = pos + (long long)p2.x * 3;
        const float* s3 = pos + (long long)p3.x * 3;
        float x00 = s0[0], x01 = s0[1], x02 = s0[2];
        float x10 = s1[0], x11 = s1[1], x12 = s1[2];
        float x20 = s2[0], x21 = s2[1], x22 = s2[2];
        float x30 = s3[0], x31 = s3[1], x32 = s3[2];
        float n0 = __int_as_float(p0.y), n1 = __int_as_float(p1.y);
        float n2 = __int_as_float(p2.y), n3 = __int_as_float(p3.y);
        a0 = fmaf(n0, x00, a0); a1 = fmaf(n0, x01, a1); a2 = fmaf(n0, x02, a2);
        a0 = fmaf(n1, x10, a0); a1 = fmaf(n1, x11, a1); a2 = fmaf(n1, x12, a2);
        a0 = fmaf(n2, x20, a0); a1 = fmaf(n2, x21, a1); a2 = fmaf(n2, x22, a2);
        a0 = fmaf(n3, x30, a0); a1 = fmaf(n3, x31, a1); a2 = fmaf(n3, x32, a2);
    }
    for (; e < end; e++) {
        int2 p = g_csr[e];
        float nrm = __int_as_float(p.y);
        const float* xs = pos + (long long)p.x * 3;
        a0 = fmaf(nrm, xs[0], a0);
        a1 = fmaf(nrm, xs[1], a1);
        a2 = fmaf(nrm, xs[2], a2);
    }
    float* o = h1 + (long long)v * 64;
#pragma unroll
    for (int j4 = 0; j4 < 16; j4++) {
        float4 r;
        float* rr = (float*)&r;
#pragma unroll
        for (int u = 0; u < 4; u++) {
            int j = j4 * 4 + u;
            float acc = sb[j];
            acc = fmaf(a0, sW[j], acc);
            acc = fmaf(a1, sW[64 + j], acc);
            acc = fmaf(a2, sW[128 + j], acc);
            rr[u] = fmaxf(acc, 0.0f);
        }
        *(float4*)(o + j4 * 4) = r;
    }
}

// ---------------- layer 2+3: gather(h1,64) + GEMM64x64 + ReLU + GEMM64x24 -----
#define L2_NPB 64   // nodes per block (8 warps x 8 iterations)
__global__ void __launch_bounds__(256)
layer2_kernel(const float* __restrict__ h1, const float* __restrict__ W2,
              const float* __restrict__ b2, const float* __restrict__ W3,
              float* __restrict__ y) {
    __shared__ float sW2[64 * 64];
    __shared__ float sW3[64 * 24];
    __shared__ float sb2[64];
    __shared__ float tile[8][64];
    int t = threadIdx.x;
    for (int i = t; i < 64 * 64; i += 256) sW2[i] = W2[i];
    for (int i = t; i < 64 * 24; i += 256) sW3[i] = W3[i];
    if (t < 64) sb2[t] = b2[t];
    __syncthreads();
    int warp = t >> 5, lane = t & 31;
#pragma unroll
    for (int it = 0; it < L2_NPB / 8; it++) {
        int v = blockIdx.x * L2_NPB + it * 8 + warp;
        if (v < N_NODES) {
            // gather: lane owns features 2*lane, 2*lane+1
            float di = g_dinv[v];
            float self = di * di;
            float2 aa = ((const float2*)(h1 + (long long)v * 64))[lane];
            float a0 = self * aa.x;
            float a1 = self * aa.y;
            int e = g_row_ptr[v], end = g_row_ptr[v + 1];
            for (; e + 4 <= end; e += 4) {
                int2 p0 = g_csr[e], p1 = g_csr[e + 1], p2 = g_csr[e + 2], p3 = g_csr[e + 3];
                float2 f0 = ((const float2*)(h1 + (long long)p0.x * 64))[lane];
                float2 f1 = ((const float2*)(h1 + (long long)p1.x * 64))[lane];
                float2 f2 = ((const float2*)(h1 + (long long)p2.x * 64))[lane];
                float2 f3 = ((const float2*)(h1 + (long long)p3.x * 64))[lane];
                float n0 = __int_as_float(p0.y), n1 = __int_as_float(p1.y);
                float n2 = __int_as_float(p2.y), n3 = __int_as_float(p3.y);
                a0 = fmaf(n0, f0.x, a0); a1 = fmaf(n0, f0.y, a1);
                a0 = fmaf(n1, f1.x, a0); a1 = fmaf(n1, f1.y, a1);
                a0 = fmaf(n2, f2.x, a0); a1 = fmaf(n2, f2.y, a1);
                a0 = fmaf(n3, f3.x, a0); a1 = fmaf(n3, f3.y, a1);
            }
            for (; e < end; e++) {
                int2 p = g_csr[e];
                float nrm = __int_as_float(p.y);
                float2 f = ((const float2*)(h1 + (long long)p.x * 64))[lane];
                a0 = fmaf(nrm, f.x, a0);
                a1 = fmaf(nrm, f.y, a1);
            }
            ((float2*)tile[warp])[lane] = make_float2(a0, a1);
            __syncwarp();
            // GEMM 64x64 + ReLU
            float c0 = sb2[lane], c1 = sb2[lane + 32];
#pragma unroll
            for (int k = 0; k < 64; k++) {
                float xk = tile[warp][k];
                c0 = fmaf(xk, sW2[k * 64 + lane], c0);
                c1 = fmaf(xk, sW2[k * 64 + lane + 32], c1);
            }
            c0 = fmaxf(c0, 0.0f);
            c1 = fmaxf(c1, 0.0f);
            __syncwarp();
            tile[warp][lane] = c0;
            tile[warp][lane + 32] = c1;
            __syncwarp();
            // GEMM 64x24 (bias deferred to final)
            if (lane < 24) {
                float acc = 0.0f;
#pragma unroll
                for (int k = 0; k < 64; k++)
                    acc = fmaf(tile[warp][k], sW3[k * 24 + lane], acc);
                y[(long long)v * 32 + lane] = acc;
            }
            __syncwarp();
        }
    }
}

// ---------------- layer 3 aggregate (dim 24, stride 32) + fused pooling -------
__global__ void __launch_bounds__(256)
gather24_pool_kernel(const float* __restrict__ y) {
    int gtid = blockIdx.x * blockDim.x + threadIdx.x;
    int v = gtid >> 5;
    int lane = gtid & 31;
    if (v >= N_NODES || lane >= 24) return;
    float di = g_dinv[v];
    float self = di * di;
    float a = self * y[(long long)v * 32 + lane];
    int e = g_row_ptr[v], end = g_row_ptr[v + 1];
    for (; e + 4 <= end; e += 4) {
        int2 p0 = g_csr[e], p1 = g_csr[e + 1], p2 = g_csr[e + 2], p3 = g_csr[e + 3];
        float x0 = y[(long long)p0.x * 32 + lane];
        float x1 = y[(long long)p1.x * 32 + lane];
        float x2 = y[(long long)p2.x * 32 + lane];
        float x3 = y[(long long)p3.x * 32 + lane];
        a = fmaf(__int_as_float(p0.y), x0, a);
        a = fmaf(__int_as_float(p1.y), x1, a);
        a = fmaf(__int_as_float(p2.y), x2, a);
        a = fmaf(__int_as_float(p3.y), x3, a);
    }
    for (; e < end; e++) {
        int2 p = g_csr[e];
        a = fmaf(__int_as_float(p.y), y[(long long)p.x * 32 + lane], a);
    }
    int g = g_batch[v];
    atomicAdd(&g_sums[g * 24 + lane], a);
}

// ---------------- final: mean + bias + tanh -----------------------------------
__global__ void final_kernel(const float* __restrict__ b3, float* __restrict__ out) {
    int i = blockIdx.x * blockDim.x + threadIdx.x;
    if (i >= N_GRAPHS * 24) return;
    int g = i / 24;
    int j = i % 24;
    float c = g_cnt[g];
    float m = (c > 0.0f) ? (g_sums[i] / c + b3[j]) : 0.0f;
    out[i] = tanhf(m);
}

// ---------------- launch -----------------------------------------------------
extern "C" void kernel_launch(void* const* d_in, const int* in_sizes, int n_in,
                              void* d_out, int out_size) {
    const float* pos   = (const float*)d_in[0];
    const int*   ei    = (const int*)d_in[1];   // int32 or int64 (detected)
    const int*   batch = (const int*)d_in[2];
    const float* W1    = (const float*)d_in[3];
    const float* b1    = (const float*)d_in[4];
    const float* W2    = (const float*)d_in[5];
    const float* b2    = (const float*)d_in[6];
    const float* W3    = (const float*)d_in[7];
    const float* b3    = (const float*)d_in[8];
    float*       out   = (float*)d_out;

    const int E = in_sizes[1] / 2;

    float* h1; cudaGetSymbolAddress((void**)&h1, g_h);
    float* y;  cudaGetSymbolAddress((void**)&y, g_y);

    const int TB = 256;
    auto grid = [&](long long n, int tb) { return (int)((n + tb - 1) / tb); };

    detect_zero_kernel<<<1, 256>>>(ei, E < 2048 ? E : 2048);
    convert_kernel<<<grid(N_NODES, TB), TB>>>(batch);
    count_deg_kernel<<<grid(E, TB), TB>>>(ei, E);
    scan1_kernel<<<N_SCANB, SCAN_B>>>();
    scan2_kernel<<<1, 32>>>();
    scan3_kernel<<<grid(N_NODES, TB), TB>>>(E);
    fill_csr_kernel<<<grid(E, TB), TB>>>(ei, E);

    layer1_kernel<<<grid(N_NODES, 128), 128>>>(pos, W1, b1, h1);
    layer2_kernel<<<grid(N_NODES, L2_NPB), 256>>>(h1, W2, b2, W3, y);
    gather24_pool_kernel<<<grid((long long)N_NODES * 32, TB), TB>>>(y);
    final_kernel<<<grid(N_GRAPHS * 24, TB), TB>>>(b3, out);
}

// round 6
// speedup vs baseline: 1.0720x; 1.0720x over previous
#include <cuda_runtime.h>
#include <cuda_bf16.h>
#include <cstdint>

#define N_NODES 100000
#define N_GRAPHS 64
#define MAX_E    1600000
#define SCAN_B   1024
#define N_SCANB  ((N_NODES + SCAN_B - 1) / SCAN_B)   // 98

// ---------------- scratch (device globals; no allocation allowed) ----------
__device__ int   g_flag64;               // 1 if index buffers are int64
__device__ int   g_batch[N_NODES];
__device__ int   g_indeg[N_NODES];
__device__ float g_dinv[N_NODES];
__device__ int   g_row_ptr[N_NODES + 1];
__device__ int   g_cur[N_NODES];
__device__ int   g_blocksum[N_SCANB];
__device__ int   g_blockoff[N_SCANB];
__device__ __align__(16) int2   g_csr[MAX_E];          // {src, nrm as int}
__device__ __align__(16) float4 g_pos4[N_NODES];       // padded pos
__device__ __align__(16) float  g_h[N_NODES * 64];     // h1 activations
__device__ __align__(16) float  g_y[N_NODES * 32];     // layer-3 pre-agg (stride 32, 24 used)
__device__ float g_sums[N_GRAPHS * 24];
__device__ float g_cnt[N_GRAPHS];

// ---------------- detect dtype + zero indeg + zero pool ---------------------
// int64 indices (< 2^31) => every odd 32-bit word is zero. 2048 samples.
__global__ void detect_zero_kernel(const int* __restrict__ buf, int samples) {
    int t = threadIdx.x;
    int v = blockIdx.x * blockDim.x + t;
    if (v < N_NODES) g_indeg[v] = 0;
    if (blockIdx.x == 0) {
        __shared__ int s_nz[256];
        int nz = 0;
        for (int i = t; i < samples; i += 256) nz |= buf[2 * i + 1];
        s_nz[t] = nz;
        __syncthreads();
        for (int off = 128; off > 0; off >>= 1) {
            if (t < off) s_nz[t] |= s_nz[t + off];
            __syncthreads();
        }
        if (t == 0) g_flag64 = (s_nz[0] == 0) ? 1 : 0;
        for (int i = t; i < N_GRAPHS * 24; i += 256) g_sums[i] = 0.0f;
        if (t < N_GRAPHS) g_cnt[t] = 0.0f;
    }
}

__device__ __forceinline__ int load_idx(const int* __restrict__ buf, long long i) {
    return g_flag64 ? buf[2 * i] : buf[(int)i];
}

// ---------------- prep: batch convert + graph counts + degree + pos4 --------
__global__ void prep_kernel(const int* __restrict__ ei, const int* __restrict__ batch,
                            const float* __restrict__ pos, int E) {
    __shared__ float scnt[N_GRAPHS];
    int t = threadIdx.x;
    int i = blockIdx.x * blockDim.x + t;
    bool node_block = (blockIdx.x * blockDim.x) < N_NODES;   // uniform per block
    if (node_block) {
        if (t < N_GRAPHS) scnt[t] = 0.0f;
        __syncthreads();
    }
    if (i < N_NODES) {
        int g = load_idx(batch, i);
        g_batch[i] = g;
        atomicAdd(&scnt[g], 1.0f);
        g_pos4[i] = make_float4(pos[3 * i], pos[3 * i + 1], pos[3 * i + 2], 0.0f);
    }
    if (i < E) {
        int d = load_idx(ei, (long long)E + i);
        atomicAdd(&g_indeg[d], 1);
    }
    if (node_block) {
        __syncthreads();
        if (t < N_GRAPHS && scnt[t] != 0.0f) atomicAdd(&g_cnt[t], scnt[t]);
    }
}

// ---------------- scan (exclusive prefix sum of indeg -> row_ptr) -------------
__global__ void scan1_kernel() {
    __shared__ int s[SCAN_B];
    int t = threadIdx.x;
    int i = blockIdx.x * SCAN_B + t;
    int v = (i < N_NODES) ? g_indeg[i] : 0;
    if (i < N_NODES) g_dinv[i] = rsqrtf((float)(v + 1));   // +1 self-loop
    s[t] = v;
    __syncthreads();
#pragma unroll
    for (int off = 1; off < SCAN_B; off <<= 1) {
        int x = (t >= off) ? s[t - off] : 0;
        __syncthreads();
        s[t] += x;
        __syncthreads();
    }
    if (i < N_NODES) g_row_ptr[i] = s[t] - v;   // exclusive
    if (t == SCAN_B - 1) g_blocksum[blockIdx.x] = s[t];
}

__global__ void scan2_kernel() {
    int lane = threadIdx.x;   // one warp
    int acc = 0;
    for (int base = 0; base < N_SCANB; base += 32) {
        int i = base + lane;
        int v0 = (i < N_SCANB) ? g_blocksum[i] : 0;
        int v = v0;
#pragma unroll
        for (int off = 1; off < 32; off <<= 1) {
            int x = __shfl_up_sync(0xFFFFFFFFu, v, off);
            if (lane >= off) v += x;
        }
        if (i < N_SCANB) g_blockoff[i] = acc + v - v0;   // exclusive
        acc += __shfl_sync(0xFFFFFFFFu, v, 31);
    }
}

__global__ void scan3_kernel(int E) {
    int i = blockIdx.x * blockDim.x + threadIdx.x;
    if (i < N_NODES) {
        int r = g_row_ptr[i] + g_blockoff[i / SCAN_B];
        g_row_ptr[i] = r;
        g_cur[i] = r;
    }
    if (i == 0) g_row_ptr[N_NODES] = E;
}

// ---------------- CSR fill ----------------------------------------------------
__global__ void fill_csr_kernel(const int* __restrict__ ei, int E) {
    int e = blockIdx.x * blockDim.x + threadIdx.x;
    if (e >= E) return;
    int s = load_idx(ei, e);
    int d = load_idx(ei, (long long)E + e);
    int pos = atomicAdd(&g_cur[d], 1);
    float nrm = g_dinv[s] * g_dinv[d];
    g_csr[pos] = make_int2(s, __float_as_int(nrm));
}

// ---------------- layer 1: gather(pos4) + GEMM 3->64 + ReLU ------------------
__global__ void __launch_bounds__(128)
layer1_kernel(const float* __restrict__ W1, const float* __restrict__ b1,
              float* __restrict__ h1) {
    __shared__ float sW[3 * 64];
    __shared__ float sb[64];
    for (int i = threadIdx.x; i < 3 * 64; i += 128) sW[i] = W1[i];
    if (threadIdx.x < 64) sb[threadIdx.x] = b1[threadIdx.x];
    __syncthreads();
    int v = blockIdx.x * 128 + threadIdx.x;
    if (v >= N_NODES) return;
    float di = g_dinv[v];
    float self = di * di;
    float4 pv = g_pos4[v];
    float a0 = self * pv.x;
    float a1 = self * pv.y;
    float a2 = self * pv.z;
    int e = g_row_ptr[v], end = g_row_ptr[v + 1];
    for (; e + 2 <= end; e += 2) {
        int2 p0 = g_csr[e], p1 = g_csr[e + 1];
        float4 f0 = g_pos4[p0.x];
        float4 f1 = g_pos4[p1.x];
        float n0 = __int_as_float(p0.y), n1 = __int_as_float(p1.y);
        a0 = fmaf(n0, f0.x, a0); a1 = fmaf(n0, f0.y, a1); a2 = fmaf(n0, f0.z, a2);
        a0 = fmaf(n1, f1.x, a0); a1 = fmaf(n1, f1.y, a1); a2 = fmaf(n1, f1.z, a2);
    }
    if (e < end) {
        int2 p = g_csr[e];
        float4 f = g_pos4[p.x];
        float nrm = __int_as_float(p.y);
        a0 = fmaf(nrm, f.x, a0); a1 = fmaf(nrm, f.y, a1); a2 = fmaf(nrm, f.z, a2);
    }
    float* o = h1 + (long long)v * 64;
#pragma unroll
    for (int j4 = 0; j4 < 16; j4++) {
        float4 r;
        float* rr = (float*)&r;
#pragma unroll
        for (int u = 0; u < 4; u++) {
            int j = j4 * 4 + u;
            float acc = sb[j];
            acc = fmaf(a0, sW[j], acc);
            acc = fmaf(a1, sW[64 + j], acc);
            acc = fmaf(a2, sW[128 + j], acc);
            rr[u] = fmaxf(acc, 0.0f);
        }
        *(float4*)(o + j4 * 4) = r;
    }
}

// ---------------- layer 2+3: gather(h1,64) + GEMM64x64 + ReLU + GEMM64x24 -----
// Half-warp per node: lane owns a float4 of features (16 lanes x 4 = 64).
#define L2_NPB 64   // nodes per block: 8 warps x 2 nodes x 4 iterations
__global__ void __launch_bounds__(256)
layer2_kernel(const float* __restrict__ h1, const float* __restrict__ W2,
              const float* __restrict__ b2, const float* __restrict__ W3,
              float* __restrict__ y) {
    __shared__ float sW2[64 * 64];
    __shared__ float sW3[64 * 24];
    __shared__ float sb2[64];
    __shared__ float tile[16][64];
    int t = threadIdx.x;
    for (int i = t; i < 64 * 64; i += 256) sW2[i] = W2[i];
    for (int i = t; i < 64 * 24; i += 256) sW3[i] = W3[i];
    if (t < 64) sb2[t] = b2[t];
    __syncthreads();
    int warp = t >> 5, lane = t & 31;
    int half = lane >> 4, q = lane & 15;
#pragma unroll
    for (int it = 0; it < L2_NPB / 16; it++) {
        int vbase = blockIdx.x * L2_NPB + it * 16 + warp * 2;
        int v = vbase + half;
        // ---- gather phase (half-warp per node, float4 per lane) ----
        float4 a = make_float4(0.0f, 0.0f, 0.0f, 0.0f);
        if (v < N_NODES) {
            float di = g_dinv[v];
            float self = di * di;
            float4 x = ((const float4*)(h1 + (long long)v * 64))[q];
            a.x = self * x.x; a.y = self * x.y; a.z = self * x.z; a.w = self * x.w;
            int e = g_row_ptr[v], end = g_row_ptr[v + 1];
            for (; e + 2 <= end; e += 2) {
                int2 p0 = g_csr[e], p1 = g_csr[e + 1];
                float4 f0 = ((const float4*)(h1 + (long long)p0.x * 64))[q];
                float4 f1 = ((const float4*)(h1 + (long long)p1.x * 64))[q];
                float n0 = __int_as_float(p0.y), n1 = __int_as_float(p1.y);
                a.x = fmaf(n0, f0.x, a.x); a.y = fmaf(n0, f0.y, a.y);
                a.z = fmaf(n0, f0.z, a.z); a.w = fmaf(n0, f0.w, a.w);
                a.x = fmaf(n1, f1.x, a.x); a.y = fmaf(n1, f1.y, a.y);
                a.z = fmaf(n1, f1.z, a.z); a.w = fmaf(n1, f1.w, a.w);
            }
            if (e < end) {
                int2 p = g_csr[e];
                float4 f = ((const float4*)(h1 + (long long)p.x * 64))[q];
                float nrm = __int_as_float(p.y);
                a.x = fmaf(nrm, f.x, a.x); a.y = fmaf(nrm, f.y, a.y);
                a.z = fmaf(nrm, f.z, a.z); a.w = fmaf(nrm, f.w, a.w);
            }
        }
        ((float4*)tile[warp * 2 + half])[q] = a;
        __syncwarp();
        // ---- GEMM phase: warp handles its 2 nodes sequentially ----
#pragma unroll
        for (int s = 0; s < 2; s++) {
            int vv = vbase + s;
            if (vv >= N_NODES) continue;
            float* row = tile[warp * 2 + s];
            float c0 = sb2[lane], c1 = sb2[lane + 32];
#pragma unroll
            for (int k = 0; k < 64; k++) {
                float xk = row[k];
                c0 = fmaf(xk, sW2[k * 64 + lane], c0);
                c1 = fmaf(xk, sW2[k * 64 + lane + 32], c1);
            }
            c0 = fmaxf(c0, 0.0f);
            c1 = fmaxf(c1, 0.0f);
            __syncwarp();
            row[lane] = c0;
            row[lane + 32] = c1;
            __syncwarp();
            if (lane < 24) {
                float acc = 0.0f;
#pragma unroll
                for (int k = 0; k < 64; k++)
                    acc = fmaf(row[k], sW3[k * 24 + lane], acc);
                y[(long long)vv * 32 + lane] = acc;
            }
            __syncwarp();
        }
    }
}

// ---------------- layer 3 aggregate (dim 24, stride 32) + fused pooling -------
__global__ void __launch_bounds__(256)
gather24_pool_kernel(const float* __restrict__ y) {
    int gtid = blockIdx.x * blockDim.x + threadIdx.x;
    int v = gtid >> 5;
    int lane = gtid & 31;
    if (v >= N_NODES || lane >= 24) return;
    float di = g_dinv[v];
    float self = di * di;
    float a = self * y[(long long)v * 32 + lane];
    int e = g_row_ptr[v], end = g_row_ptr[v + 1];
    for (; e + 4 <= end; e += 4) {
        int2 p0 = g_csr[e], p1 = g_csr[e + 1], p2 = g_csr[e + 2], p3 = g_csr[e + 3];
        float x0 = y[(long long)p0.x * 32 + lane];
        float x1 = y[(long long)p1.x * 32 + lane];
        float x2 = y[(long long)p2.x * 32 + lane];
        float x3 = y[(long long)p3.x * 32 + lane];
        a = fmaf(__int_as_float(p0.y), x0, a);
        a = fmaf(__int_as_float(p1.y), x1, a);
        a = fmaf(__int_as_float(p2.y), x2, a);
        a = fmaf(__int_as_float(p3.y), x3, a);
    }
    for (; e < end; e++) {
        int2 p = g_csr[e];
        a = fmaf(__int_as_float(p.y), y[(long long)p.x * 32 + lane], a);
    }
    int g = g_batch[v];
    atomicAdd(&g_sums[g * 24 + lane], a);
}

// ---------------- final: mean + bias + tanh -----------------------------------
__global__ void final_kernel(const float* __restrict__ b3, float* __restrict__ out) {
    int i = blockIdx.x * blockDim.x + threadIdx.x;
    if (i >= N_GRAPHS * 24) return;
    int g = i / 24;
    int j = i % 24;
    float c = g_cnt[g];
    float m = (c > 0.0f) ? (g_sums[i] / c + b3[j]) : 0.0f;
    out[i] = tanhf(m);
}

// ---------------- launch -----------------------------------------------------
extern "C" void kernel_launch(void* const* d_in, const int* in_sizes, int n_in,
                              void* d_out, int out_size) {
    const float* pos   = (const float*)d_in[0];
    const int*   ei    = (const int*)d_in[1];   // int32 or int64 (detected)
    const int*   batch = (const int*)d_in[2];
    const float* W1    = (const float*)d_in[3];
    const float* b1    = (const float*)d_in[4];
    const float* W2    = (const float*)d_in[5];
    const float* b2    = (const float*)d_in[6];
    const float* W3    = (const float*)d_in[7];
    const float* b3    = (const float*)d_in[8];
    float*       out   = (float*)d_out;

    const int E = in_sizes[1] / 2;

    float* h1; cudaGetSymbolAddress((void**)&h1, g_h);
    float* y;  cudaGetSymbolAddress((void**)&y, g_y);

    const int TB = 256;
    auto grid = [&](long long n, int tb) { return (int)((n + tb - 1) / tb); };

    detect_zero_kernel<<<grid(N_NODES, TB), TB>>>(ei, E < 2048 ? E : 2048);
    prep_kernel<<<grid(E, TB), TB>>>(ei, batch, pos, E);
    scan1_kernel<<<N_SCANB, SCAN_B>>>();
    scan2_kernel<<<1, 32>>>();
    scan3_kernel<<<grid(N_NODES, TB), TB>>>(E);
    fill_csr_kernel<<<grid(E, TB), TB>>>(ei, E);

    layer1_kernel<<<grid(N_NODES, 128), 128>>>(W1, b1, h1);
    layer2_kernel<<<grid(N_NODES, L2_NPB), 256>>>(h1, W2, b2, W3, y);
    gather24_pool_kernel<<<grid((long long)N_NODES * 32, TB), TB>>>(y);
    final_kernel<<<grid(N_GRAPHS * 24, TB), TB>>>(b3, out);
}